// round 8
// baseline (speedup 1.0000x reference)
#include <cuda_runtime.h>
#include <cstdint>

// FMLayer: out[b, p] = wdot[p] * x[b, j1(p)] * x[b, j2(p)]
//   N_FEATURES = 512, K = 4, BATCH = 1024, P = 130816 (upper triangle, row-major by j1)
// DRAM-write-bound: 535.8 MB out per launch (~67 us floor @ 8 TB/s).
// R7: BT=4/TPB=512 -> 83.8us, DRAM 73%. This round: BT=8/TPB=1024 (64 KB
// dynamic smem, 2 blocks/SM, still 100% theoretical occ) halves table + fill
// overhead per stored byte while keeping R7's wave structure.

#define NF    512
#define BATCH 1024
#define NPAIR 130816              // 512*511/2
#define NQ4   (NPAIR / 4)         // 32704 float4 slots per batch row
#define BT    8                   // batch rows per block
#define TPB   1024                // threads per block
#define SMEM_BYTES (BT * 4 * NF * 4)   // 64 KB

// Scratch (allocation-free rule: __device__ globals)
__device__ __align__(16) float g_wdot[NPAIR];
__device__ __align__(16) int   g_jidx[NPAIR];   // (j1<<16)|j2 per pair (slow path)
__device__ __align__(16) int   g_meta[NQ4];     // (j1<<16)|j2start, or -1 if row-crossing

__device__ __forceinline__ int tri_off(int j) {
    return (NF - 1) * j - ((j * (j - 1)) >> 1);
}

// largest j1 with tri_off(j1) <= p ; j1 in [0,510] -> 9 branch-free steps, int-only
__device__ __forceinline__ int find_row(int p) {
    int lo = 0, hi = NF - 2;
    #pragma unroll
    for (int it = 0; it < 9; it++) {
        int mid = (lo + hi + 1) >> 1;
        if (tri_off(mid) <= p) lo = mid; else hi = mid - 1;
    }
    return lo;
}

// One thread per float4-slot q: recover (j1,j2) for p=4q, walk 4 pairs
// incrementally (exact row-crossing handling), emit wdot4/jidx4/meta.
__global__ void __launch_bounds__(256) fm_setup_kernel(const float* __restrict__ w) {
    int q = blockIdx.x * blockDim.x + threadIdx.x;
    if (q >= NQ4) return;

    int p  = 4 * q;
    int j1 = find_row(p);
    int j2 = p - tri_off(j1) + j1 + 1;

    const float4* w4 = reinterpret_cast<const float4*>(w);  // 8 KB, L1-resident
    float4 wa = __ldg(&w4[j1]);

    int   r1 = j1, r2 = j2;
    int   jj[4];
    float wdv[4];
    #pragma unroll
    for (int e = 0; e < 4; e++) {
        if (r2 >= NF) { r1++; r2 = r1 + 1; wa = __ldg(&w4[r1]); }
        float4 wb = __ldg(&w4[r2]);
        wdv[e] = wa.x * wb.x + wa.y * wb.y + wa.z * wb.z + wa.w * wb.w;
        jj[e]  = (r1 << 16) | r2;
        r2++;
    }

    reinterpret_cast<float4*>(g_wdot)[q] = make_float4(wdv[0], wdv[1], wdv[2], wdv[3]);
    reinterpret_cast<int4*>(g_jidx)[q]   = make_int4(jj[0], jj[1], jj[2], jj[3]);
    g_meta[q] = ((jj[0] >> 16) == (jj[3] >> 16)) ? jj[0] : -1;
}

// Block = (chunk of 2048 float4 slots) x (BT=8 batch rows). 1024 threads, 2 slots each.
// Dynamic smem 64 KB: 4 shifted copies of each of 8 x rows (aligned LDS.128).
// 2 blocks/SM (thread-limited) = 2048 thr = 100% theoretical occupancy.
__global__ void __launch_bounds__(TPB, 2) fm_main_kernel(
    const float* __restrict__ x, float* __restrict__ out)
{
    extern __shared__ float xs[];     // [BT][4][NF]

    const int b0 = blockIdx.y * BT;

    for (int i = threadIdx.x; i < BT * NF; i += TPB) {
        int bb = i >> 9;              // / NF
        int j  = i & (NF - 1);
        float v = x[(size_t)(b0 + bb) * NF + j];
        float* row = xs + ((bb << 2) << 9);   // xs[bb][0]
        #pragma unroll
        for (int a = 0; a < 4; a++)
            if (j >= a) row[(a << 9) + j - a] = v;
    }
    __syncthreads();

    const int4*   jid4 = reinterpret_cast<const int4*>(g_jidx);
    const float4* wd4  = reinterpret_cast<const float4*>(g_wdot);
    float4* ob0 = reinterpret_cast<float4*>(out) + (size_t)b0 * NQ4;

    const int qbase = blockIdx.x * (TPB * 2) + threadIdx.x;

    #pragma unroll
    for (int u = 0; u < 2; u++) {
        int q = qbase + u * TPB;
        if (q >= NQ4) continue;       // only last chunk partially masked
        int    mu = __ldg(&g_meta[q]);
        float4 wv = __ldg(&wd4[q]);

        if (mu >= 0) {
            // fast path: all 4 pairs share j1, j2..j2+3 contiguous
            int j1  = mu >> 16;
            int j2s = mu & 0xffff;
            int a   = j2s & 3;
            int idx = (((a << 9) + j2s - a) >> 2);   // float4 index into xs[bb][a]
            #pragma unroll
            for (int bb = 0; bb < BT; bb++) {
                const float* row = xs + ((bb << 2) << 9);
                float  s  = row[j1];
                float4 xv = reinterpret_cast<const float4*>(row)[idx];
                float4 r;
                r.x = s * wv.x * xv.x;
                r.y = s * wv.y * xv.y;
                r.z = s * wv.z * xv.z;
                r.w = s * wv.w * xv.w;
                __stcs(&ob0[(size_t)bb * NQ4 + q], r);
            }
        } else {
            // slow path (1.6% of slots): row-crossing, per-element gather
            int4 j = __ldg(&jid4[q]);
            #pragma unroll
            for (int bb = 0; bb < BT; bb++) {
                const float* xr = xs + ((bb << 2) << 9);
                float4 r;
                r.x = wv.x * xr[j.x >> 16] * xr[j.x & 0xffff];
                r.y = wv.y * xr[j.y >> 16] * xr[j.y & 0xffff];
                r.z = wv.z * xr[j.z >> 16] * xr[j.z & 0xffff];
                r.w = wv.w * xr[j.w >> 16] * xr[j.w & 0xffff];
                __stcs(&ob0[(size_t)bb * NQ4 + q], r);
            }
        }
    }
}

extern "C" void kernel_launch(void* const* d_in, const int* in_sizes, int n_in,
                              void* d_out, int out_size)
{
    const float* x = (const float*)d_in[0];   // [1024, 512]
    const float* w = (const float*)d_in[1];   // [512, 4]
    float* out = (float*)d_out;               // [1024, 130816]
    (void)in_sizes; (void)n_in; (void)out_size;

    // raise dynamic smem limit (host-side attribute set; not a stream op)
    cudaFuncSetAttribute(fm_main_kernel,
                         cudaFuncAttributeMaxDynamicSharedMemorySize, SMEM_BYTES);

    fm_setup_kernel<<<(NQ4 + 255) / 256, 256>>>(w);

    dim3 grid(16, BATCH / BT);   // 16 * 2048 f4 = 32768 >= 32704 (guarded)
    fm_main_kernel<<<grid, TPB, SMEM_BYTES>>>(x, out);
}

// round 9
// speedup vs baseline: 1.0230x; 1.0230x over previous
#include <cuda_runtime.h>
#include <cstdint>

// FMLayer: out[b, p] = wdot[p] * x[b, j1(p)] * x[b, j2(p)]
//   N_FEATURES = 512, K = 4, BATCH = 1024, P = 130816 (upper triangle, row-major by j1)
// DRAM-write-bound: 535.8 MB out per launch (~67 us floor @ 8 TB/s).
// R8 lesson: 1024-thr blocks regress; R7 shape (TPB=512, BT=4, 4 blk/SM) is
// the tiling optimum. This round: hoist all table LDGs (meta+wdot, MLP=8) to
// kernel start so their L2 latency hides under the smem fill + barrier.

#define NF    512
#define BATCH 1024
#define NPAIR 130816              // 512*511/2
#define NQ4   (NPAIR / 4)         // 32704 float4 slots per batch row
#define BT    4                   // batch rows per block
#define TPB   512                 // threads per block

// Scratch (allocation-free rule: __device__ globals)
__device__ __align__(16) float g_wdot[NPAIR];
__device__ __align__(16) int   g_jidx[NPAIR];   // (j1<<16)|j2 per pair (slow path)
__device__ __align__(16) int   g_meta[NQ4];     // (j1<<16)|j2start, or -1 if row-crossing

__device__ __forceinline__ int tri_off(int j) {
    return (NF - 1) * j - ((j * (j - 1)) >> 1);
}

// largest j1 with tri_off(j1) <= p ; j1 in [0,510] -> 9 branch-free steps, int-only
__device__ __forceinline__ int find_row(int p) {
    int lo = 0, hi = NF - 2;
    #pragma unroll
    for (int it = 0; it < 9; it++) {
        int mid = (lo + hi + 1) >> 1;
        if (tri_off(mid) <= p) lo = mid; else hi = mid - 1;
    }
    return lo;
}

// One thread per float4-slot q: recover (j1,j2) for p=4q, walk 4 pairs
// incrementally (exact row-crossing handling), emit wdot4/jidx4/meta.
__global__ void __launch_bounds__(256) fm_setup_kernel(const float* __restrict__ w) {
    int q = blockIdx.x * blockDim.x + threadIdx.x;
    if (q >= NQ4) return;

    int p  = 4 * q;
    int j1 = find_row(p);
    int j2 = p - tri_off(j1) + j1 + 1;

    const float4* w4 = reinterpret_cast<const float4*>(w);  // 8 KB, L1-resident
    float4 wa = __ldg(&w4[j1]);

    int   r1 = j1, r2 = j2;
    int   jj[4];
    float wdv[4];
    #pragma unroll
    for (int e = 0; e < 4; e++) {
        if (r2 >= NF) { r1++; r2 = r1 + 1; wa = __ldg(&w4[r1]); }
        float4 wb = __ldg(&w4[r2]);
        wdv[e] = wa.x * wb.x + wa.y * wb.y + wa.z * wb.z + wa.w * wb.w;
        jj[e]  = (r1 << 16) | r2;
        r2++;
    }

    reinterpret_cast<float4*>(g_wdot)[q] = make_float4(wdv[0], wdv[1], wdv[2], wdv[3]);
    reinterpret_cast<int4*>(g_jidx)[q]   = make_int4(jj[0], jj[1], jj[2], jj[3]);
    g_meta[q] = ((jj[0] >> 16) == (jj[3] >> 16)) ? jj[0] : -1;
}

// Block = (chunk of 2048 float4 slots) x (BT=4 batch rows). 512 threads, 4 slots each.
// Table loads (meta+wdot) issued BEFORE the fill loop: latency hidden by
// fill + __syncthreads. Shared: 4 shifted copies per x row -> aligned LDS.128.
__global__ void __launch_bounds__(TPB, 4) fm_main_kernel(
    const float* __restrict__ x, float* __restrict__ out)
{
    __shared__ float xs[BT][4][NF];   // xs[b][a][i] = x_row_b[a + i]; 32 KB

    const int b0 = blockIdx.y * BT;
    const int qbase = blockIdx.x * (TPB * 4) + threadIdx.x;

    // ---- issue all table loads up front (MLP=8), clamped for the tail ----
    const float4* wd4 = reinterpret_cast<const float4*>(g_wdot);
    int    mu[4];
    float4 wv[4];
    #pragma unroll
    for (int u = 0; u < 4; u++) {
        int qc = qbase + u * TPB;
        qc = (qc < NQ4) ? qc : (NQ4 - 1);          // safe clamp; masked at store
        mu[u] = __ldg(&g_meta[qc]);
        wv[u] = __ldg(&wd4[qc]);
    }

    // ---- smem fill (hides the table-load latency) ----
    for (int i = threadIdx.x; i < BT * NF; i += TPB) {
        int bb = i >> 9;              // / NF
        int j  = i & (NF - 1);
        float v = x[(size_t)(b0 + bb) * NF + j];
        #pragma unroll
        for (int a = 0; a < 4; a++)
            if (j >= a) xs[bb][a][j - a] = v;
    }
    __syncthreads();

    const int4* jid4 = reinterpret_cast<const int4*>(g_jidx);
    float4* ob0 = reinterpret_cast<float4*>(out) + (size_t)b0 * NQ4;

    #pragma unroll
    for (int u = 0; u < 4; u++) {
        int q = qbase + u * TPB;
        if (q >= NQ4) continue;       // only last chunk partially masked
        float4 w4v = wv[u];

        if (mu[u] >= 0) {
            // fast path: all 4 pairs share j1, j2..j2+3 contiguous
            int j1  = mu[u] >> 16;
            int j2s = mu[u] & 0xffff;
            int a   = j2s & 3;
            int idx = (j2s - a) >> 2;
            #pragma unroll
            for (int bb = 0; bb < BT; bb++) {
                float  s  = xs[bb][0][j1];
                float4 xv = reinterpret_cast<const float4*>(xs[bb][a])[idx];
                float4 r;
                r.x = s * w4v.x * xv.x;
                r.y = s * w4v.y * xv.y;
                r.z = s * w4v.z * xv.z;
                r.w = s * w4v.w * xv.w;
                __stcs(&ob0[(size_t)bb * NQ4 + q], r);
            }
        } else {
            // slow path (1.6% of slots): row-crossing, per-element gather
            int4 j = __ldg(&jid4[q]);
            #pragma unroll
            for (int bb = 0; bb < BT; bb++) {
                const float* xr = xs[bb][0];
                float4 r;
                r.x = w4v.x * xr[j.x >> 16] * xr[j.x & 0xffff];
                r.y = w4v.y * xr[j.y >> 16] * xr[j.y & 0xffff];
                r.z = w4v.z * xr[j.z >> 16] * xr[j.z & 0xffff];
                r.w = w4v.w * xr[j.w >> 16] * xr[j.w & 0xffff];
                __stcs(&ob0[(size_t)bb * NQ4 + q], r);
            }
        }
    }
}

extern "C" void kernel_launch(void* const* d_in, const int* in_sizes, int n_in,
                              void* d_out, int out_size)
{
    const float* x = (const float*)d_in[0];   // [1024, 512]
    const float* w = (const float*)d_in[1];   // [512, 4]
    float* out = (float*)d_out;               // [1024, 130816]
    (void)in_sizes; (void)n_in; (void)out_size;

    fm_setup_kernel<<<(NQ4 + 255) / 256, 256>>>(w);

    dim3 grid(16, BATCH / BT);   // 16 * 2048 f4 = 32768 >= 32704 (guarded)
    fm_main_kernel<<<grid, TPB>>>(x, out);
}

// round 10
// speedup vs baseline: 1.1178x; 1.0927x over previous
#include <cuda_runtime.h>
#include <cstdint>

// FMLayer: out[b, p] = wdot[p] * x[b, j1(p)] * x[b, j2(p)]
//   N_FEATURES = 512, K = 4, BATCH = 1024, P = 130816 (upper triangle, row-major by j1)
// DRAM-write-bound: 535.8 MB out per launch (~67 us floor @ 8 TB/s).
// R9 lesson: any perturbation of the R7 hot loop regresses. This round keeps
// the R7 kernel byte-identical and overlaps the setup kernel with the main
// kernel's table-independent smem-fill phase via PDL (programmatic dependent
// launch): main blocks launch early, fill smem, then grid-sync before reading
// the tables.

#define NF    512
#define BATCH 1024
#define NPAIR 130816              // 512*511/2
#define NQ4   (NPAIR / 4)         // 32704 float4 slots per batch row
#define BT    4                   // batch rows per block
#define TPB   512                 // threads per block

// Scratch (allocation-free rule: __device__ globals)
__device__ __align__(16) float g_wdot[NPAIR];
__device__ __align__(16) int   g_jidx[NPAIR];   // (j1<<16)|j2 per pair (slow path)
__device__ __align__(16) int   g_meta[NQ4];     // (j1<<16)|j2start, or -1 if row-crossing

__device__ __forceinline__ int tri_off(int j) {
    return (NF - 1) * j - ((j * (j - 1)) >> 1);
}

// largest j1 with tri_off(j1) <= p ; j1 in [0,510] -> 9 branch-free steps, int-only
__device__ __forceinline__ int find_row(int p) {
    int lo = 0, hi = NF - 2;
    #pragma unroll
    for (int it = 0; it < 9; it++) {
        int mid = (lo + hi + 1) >> 1;
        if (tri_off(mid) <= p) lo = mid; else hi = mid - 1;
    }
    return lo;
}

// One thread per float4-slot q: recover (j1,j2) for p=4q, walk 4 pairs
// incrementally (exact row-crossing handling), emit wdot4/jidx4/meta.
__global__ void __launch_bounds__(256) fm_setup_kernel(const float* __restrict__ w) {
    int q = blockIdx.x * blockDim.x + threadIdx.x;
    if (q >= NQ4) return;

    int p  = 4 * q;
    int j1 = find_row(p);
    int j2 = p - tri_off(j1) + j1 + 1;

    const float4* w4 = reinterpret_cast<const float4*>(w);  // 8 KB, L1-resident
    float4 wa = __ldg(&w4[j1]);

    int   r1 = j1, r2 = j2;
    int   jj[4];
    float wdv[4];
    #pragma unroll
    for (int e = 0; e < 4; e++) {
        if (r2 >= NF) { r1++; r2 = r1 + 1; wa = __ldg(&w4[r1]); }
        float4 wb = __ldg(&w4[r2]);
        wdv[e] = wa.x * wb.x + wa.y * wb.y + wa.z * wb.z + wa.w * wb.w;
        jj[e]  = (r1 << 16) | r2;
        r2++;
    }

    reinterpret_cast<float4*>(g_wdot)[q] = make_float4(wdv[0], wdv[1], wdv[2], wdv[3]);
    reinterpret_cast<int4*>(g_jidx)[q]   = make_int4(jj[0], jj[1], jj[2], jj[3]);
    g_meta[q] = ((jj[0] >> 16) == (jj[3] >> 16)) ? jj[0] : -1;
}

// Block = (chunk of 2048 float4 slots) x (BT=4 batch rows). 512 threads, 4 slots each.
// R7-proven body. PDL: fill smem first (table-independent), then
// cudaGridDependencySynchronize() before reading g_meta/g_wdot.
__global__ void __launch_bounds__(TPB, 4) fm_main_kernel(
    const float* __restrict__ x, float* __restrict__ out)
{
    __shared__ float xs[BT][4][NF];   // xs[b][a][i] = x_row_b[a + i]; 32 KB

    const int b0 = blockIdx.y * BT;

    for (int i = threadIdx.x; i < BT * NF; i += TPB) {
        int bb = i >> 9;              // / NF
        int j  = i & (NF - 1);
        float v = x[(size_t)(b0 + bb) * NF + j];
        #pragma unroll
        for (int a = 0; a < 4; a++)
            if (j >= a) xs[bb][a][j - a] = v;
    }
    __syncthreads();

    // wait for fm_setup_kernel (PDL): tables valid beyond this point
    cudaGridDependencySynchronize();

    const int4*   jid4 = reinterpret_cast<const int4*>(g_jidx);
    const float4* wd4  = reinterpret_cast<const float4*>(g_wdot);
    float4* ob0 = reinterpret_cast<float4*>(out) + (size_t)b0 * NQ4;

    const int qbase = blockIdx.x * (TPB * 4) + threadIdx.x;

    #pragma unroll
    for (int u = 0; u < 4; u++) {
        int q = qbase + u * TPB;
        if (q >= NQ4) continue;       // only last chunk partially masked
        int    mu = __ldg(&g_meta[q]);
        float4 wv = __ldg(&wd4[q]);

        if (mu >= 0) {
            // fast path: all 4 pairs share j1, j2..j2+3 contiguous
            int j1  = mu >> 16;
            int j2s = mu & 0xffff;
            int a   = j2s & 3;
            int idx = (j2s - a) >> 2;
            #pragma unroll
            for (int bb = 0; bb < BT; bb++) {
                float  s  = xs[bb][0][j1];
                float4 xv = reinterpret_cast<const float4*>(xs[bb][a])[idx];
                float4 r;
                r.x = s * wv.x * xv.x;
                r.y = s * wv.y * xv.y;
                r.z = s * wv.z * xv.z;
                r.w = s * wv.w * xv.w;
                __stcs(&ob0[(size_t)bb * NQ4 + q], r);
            }
        } else {
            // slow path (1.6% of slots): row-crossing, per-element gather
            int4 j = __ldg(&jid4[q]);
            #pragma unroll
            for (int bb = 0; bb < BT; bb++) {
                const float* xr = xs[bb][0];
                float4 r;
                r.x = wv.x * xr[j.x >> 16] * xr[j.x & 0xffff];
                r.y = wv.y * xr[j.y >> 16] * xr[j.y & 0xffff];
                r.z = wv.z * xr[j.z >> 16] * xr[j.z & 0xffff];
                r.w = wv.w * xr[j.w >> 16] * xr[j.w & 0xffff];
                __stcs(&ob0[(size_t)bb * NQ4 + q], r);
            }
        }
    }
}

extern "C" void kernel_launch(void* const* d_in, const int* in_sizes, int n_in,
                              void* d_out, int out_size)
{
    const float* x = (const float*)d_in[0];   // [1024, 512]
    const float* w = (const float*)d_in[1];   // [512, 4]
    float* out = (float*)d_out;               // [1024, 130816]
    (void)in_sizes; (void)n_in; (void)out_size;

    fm_setup_kernel<<<(NQ4 + 255) / 256, 256>>>(w);

    // PDL launch: main kernel's blocks may start before setup completes;
    // they grid-sync before touching the tables.
    dim3 grid(16, BATCH / BT);   // 16 * 2048 f4 = 32768 >= 32704 (guarded)

    cudaLaunchConfig_t cfg = {};
    cfg.gridDim  = grid;
    cfg.blockDim = dim3(TPB, 1, 1);
    cfg.dynamicSmemBytes = 0;
    cfg.stream = 0;
    cudaLaunchAttribute attrs[1];
    attrs[0].id = cudaLaunchAttributeProgrammaticStreamSerialization;
    attrs[0].val.programmaticStreamSerializationAllowed = 1;
    cfg.attrs = attrs;
    cfg.numAttrs = 1;
    cudaLaunchKernelEx(&cfg, fm_main_kernel, x, out);
}